// round 1
// baseline (speedup 1.0000x reference)
#include <cuda_runtime.h>
#include <cstdint>

#define E 128
#define F 32
// smem layout (dynamic):
//   C0s   : 16384 floats (65536 B)   offset 0
//   ks    : 32*129 uints (16512 B)   offset 65536   (monotone keys, transposed, padded stride 129)
//   ranks : 32*128 ints  (16384 B)   offset 82048
#define SMEM_C0     0
#define SMEM_KS     65536
#define SMEM_RANK   82048
#define SMEM_TOTAL  98432

__device__ float g_C0[E * E];

// Monotone map float -> uint preserving < order (no NaNs in input)
__device__ __forceinline__ unsigned mono_key(float x) {
    unsigned u = __float_as_uint(x);
    return u ^ ((unsigned)((int)u >> 31) | 0x80000000u);
}

// ---------------------------------------------------------------------------
// Build the fixed table C0[a,b] = (W0^2)[a,b] - s0[a]*s0[b]/(E-1),
// W0[a,b] = 1/(|a-b|+1), s0[a] = sum_b W0[b,a].
// grid(128), block(128): block a, thread b computes one entry.
// ---------------------------------------------------------------------------
__global__ void build_c0_kernel() {
    __shared__ float inv[E];
    __shared__ float s0[E];
    int a = blockIdx.x;
    int b = threadIdx.x;
    inv[b] = 1.0f / (float)(b + 1);
    __syncthreads();
    float s = 0.0f;
    #pragma unroll 8
    for (int m = 0; m < E; ++m) s += inv[abs(m - b)];
    s0[b] = s;
    __syncthreads();
    float g = 0.0f;
    #pragma unroll 8
    for (int m = 0; m < E; ++m) g += inv[abs(m - a)] * inv[abs(m - b)];
    g_C0[a * E + b] = g - s0[a] * s0[b] * (1.0f / (float)(E - 1));
}

// ---------------------------------------------------------------------------
// Main kernel: one CTA per batch element. 1024 threads = 32 warps.
//   Phase 0: stage input keys (transposed, padded) + C0 table into smem
//   Phase 1: ranks. warp w handles freq f=w; lane handles 4 electrodes.
//            rank[e] = #{m : key_m < key_e} + #{m<e : key_m == key_e}
//            (== stable double-argsort of the reference)
//   Phase 2: out[j,k] = (1/F) * sum_f C0[rank_fj, rank_fk], 16 register
//            accumulators per thread; warp-uniform row -> broadcast row rank,
//            data-dependent column gather from smem.
// ---------------------------------------------------------------------------
__global__ __launch_bounds__(1024, 1)
void spearman_main_kernel(const float* __restrict__ de, float* __restrict__ out) {
    extern __shared__ char smem[];
    float*    C0s   = (float*)(smem + SMEM_C0);
    unsigned* ks    = (unsigned*)(smem + SMEM_KS);
    int*      ranks = (int*)(smem + SMEM_RANK);

    const int t = threadIdx.x;
    const int b = blockIdx.x;
    const int w = t >> 5;       // warp id == frequency band
    const int l = t & 31;       // lane

    // ---- Phase 0a: load de[b] (4096 floats) as float4, store transposed keys
    {
        const float4* din4 = (const float4*)(de + (size_t)b * (E * F));
        float4 v = din4[t];                 // elements e = t/8, f = (t%8)*4 .. +3
        int e  = t >> 3;
        int f0 = (t & 7) << 2;
        ks[(f0 + 0) * 129 + e] = mono_key(v.x);
        ks[(f0 + 1) * 129 + e] = mono_key(v.y);
        ks[(f0 + 2) * 129 + e] = mono_key(v.z);
        ks[(f0 + 3) * 129 + e] = mono_key(v.w);
    }
    // ---- Phase 0b: load C0 table (16384 floats) via float4
    {
        const float4* c4 = (const float4*)g_C0;
        float4* s4 = (float4*)C0s;
        #pragma unroll
        for (int i = 0; i < 4; ++i) s4[t + 1024 * i] = c4[t + 1024 * i];
    }
    __syncthreads();

    // ---- Phase 1: ranks. warp w -> freq w; lane handles e = l, l+32, l+64, l+96
    {
        const unsigned* krow = ks + w * 129;
        unsigned ke0 = krow[l];
        unsigned ke1 = krow[l + 32];
        unsigned ke2 = krow[l + 64];
        unsigned ke3 = krow[l + 96];
        int c0 = 0, c1 = 0, c2 = 0, c3 = 0;
        #pragma unroll 16
        for (int m = 0; m < E; ++m) {
            unsigned km = krow[m];          // warp-uniform -> broadcast
            c0 += (km < ke0) + ((km == ke0) & (m < l));
            c1 += (km < ke1) + ((km == ke1) & (m < l + 32));
            c2 += (km < ke2) + ((km == ke2) & (m < l + 64));
            c3 += (km < ke3) + ((km == ke3) & (m < l + 96));
        }
        int* rrow = ranks + w * E;
        rrow[l]      = c0;
        rrow[l + 32] = c1;
        rrow[l + 64] = c2;
        rrow[l + 96] = c3;
    }
    __syncthreads();

    // ---- Phase 2: gather-accumulate.
    // Warp w owns rows j = 4w..4w+3; lane owns cols k = l, l+32, l+64, l+96.
    float acc[4][4];
    #pragma unroll
    for (int i = 0; i < 4; ++i)
        #pragma unroll
        for (int j = 0; j < 4; ++j) acc[i][j] = 0.0f;

    const int row0 = w << 2;
    for (int f = 0; f < F; ++f) {
        const int* rrow = ranks + f * E;
        int ck0 = rrow[l];
        int ck1 = rrow[l + 32];
        int ck2 = rrow[l + 64];
        int ck3 = rrow[l + 96];
        #pragma unroll
        for (int jr = 0; jr < 4; ++jr) {
            int rj = rrow[row0 + jr];               // warp-uniform broadcast
            const float* Cr = C0s + (rj << 7);
            acc[jr][0] += Cr[ck0];
            acc[jr][1] += Cr[ck1];
            acc[jr][2] += Cr[ck2];
            acc[jr][3] += Cr[ck3];
        }
    }

    // ---- Writeout (coalesced), mean over F
    float* o = out + (size_t)b * (E * E);
    #pragma unroll
    for (int jr = 0; jr < 4; ++jr) {
        float* orow = o + (row0 + jr) * E;
        orow[l]      = acc[jr][0] * (1.0f / F);
        orow[l + 32] = acc[jr][1] * (1.0f / F);
        orow[l + 64] = acc[jr][2] * (1.0f / F);
        orow[l + 96] = acc[jr][3] * (1.0f / F);
    }
}

extern "C" void kernel_launch(void* const* d_in, const int* in_sizes, int n_in,
                              void* d_out, int out_size) {
    const float* de = (const float*)d_in[0];
    float* out = (float*)d_out;
    int B = in_sizes[0] / (E * F);

    cudaFuncSetAttribute(spearman_main_kernel,
                         cudaFuncAttributeMaxDynamicSharedMemorySize, SMEM_TOTAL);

    build_c0_kernel<<<E, E>>>();
    spearman_main_kernel<<<B, 1024, SMEM_TOTAL>>>(de, out);
}

// round 2
// speedup vs baseline: 1.3468x; 1.3468x over previous
#include <cuda_runtime.h>
#include <cstdint>

#define E 128
#define F 32
typedef unsigned long long u64;

// smem layout (dynamic, bytes):
//   C0s   : 16384 floats            [0, 65536)
//   ks64  : 32*129 u64 keys         [65536, 98560)   (transposed, padded stride 129)
//   ranks : 32*128 ints             [98560, 114944)
// After phase 2, the whole region is reused as the staging tile
//   T     : 128*129 floats          [0, 66048)
#define SMEM_C0     0
#define SMEM_KS     65536
#define SMEM_RANK   98560
#define SMEM_TOTAL  114944

__device__ float g_C0[E * E];

// Monotone map float -> uint preserving < order (no NaNs in input)
__device__ __forceinline__ unsigned mono_key(float x) {
    unsigned u = __float_as_uint(x);
    return u ^ ((unsigned)((int)u >> 31) | 0x80000000u);
}

// ---------------------------------------------------------------------------
// Fixed table C0[a,b] = (W0^2)[a,b] - s0[a]*s0[b]/(E-1),
// W0[a,b] = 1/(|a-b|+1), s0[a] = sum_b W0[b,a].
// ---------------------------------------------------------------------------
__global__ void build_c0_kernel() {
    __shared__ float inv[E];
    __shared__ float s0[E];
    int a = blockIdx.x;
    int b = threadIdx.x;
    inv[b] = 1.0f / (float)(b + 1);
    __syncthreads();
    float s = 0.0f;
    #pragma unroll 8
    for (int m = 0; m < E; ++m) s += inv[abs(m - b)];
    s0[b] = s;
    __syncthreads();
    float g = 0.0f;
    #pragma unroll 8
    for (int m = 0; m < E; ++m) g += inv[abs(m - a)] * inv[abs(m - b)];
    g_C0[a * E + b] = g - s0[a] * s0[b] * (1.0f / (float)(E - 1));
}

// ---------------------------------------------------------------------------
// Main kernel: one CTA per batch. 1024 threads = 32 warps.
// Phase 1: ranks via 64-bit keys (mono<<7 | e): one strict-< == stable rank.
// Phase 2: upper triangle only. Warp w owns rows {2w,2w+1,126-2w,127-2w};
//          aligned 32-col groups; exactly 10 gather-groups per warp.
// Phase 3: stage to smem tile (stride 129), mirror-read (conflict-free:
//          bank(T[j,k]) = bank(T[k,j]) = (j+k)%32), coalesced writeout.
// ---------------------------------------------------------------------------
__global__ __launch_bounds__(1024, 1)
void spearman_main_kernel(const float* __restrict__ de, float* __restrict__ out) {
    extern __shared__ char smem[];
    float* C0s   = (float*)(smem + SMEM_C0);
    u64*   ks    = (u64*)  (smem + SMEM_KS);
    int*   ranks = (int*)  (smem + SMEM_RANK);
    float* T     = (float*)(smem + SMEM_C0);   // reuse after phase 2

    const int t = threadIdx.x;
    const int b = blockIdx.x;
    const int w = t >> 5;       // warp id == frequency band (phase 1)
    const int l = t & 31;       // lane

    // ---- Phase 0a: load de[b] as float4, store transposed 64-bit keys
    {
        const float4* din4 = (const float4*)(de + (size_t)b * (E * F));
        float4 v = din4[t];                 // e = t/8, f = (t%8)*4 .. +3
        int e  = t >> 3;
        int f0 = (t & 7) << 2;
        ks[(f0 + 0) * 129 + e] = ((u64)mono_key(v.x) << 7) | (unsigned)e;
        ks[(f0 + 1) * 129 + e] = ((u64)mono_key(v.y) << 7) | (unsigned)e;
        ks[(f0 + 2) * 129 + e] = ((u64)mono_key(v.z) << 7) | (unsigned)e;
        ks[(f0 + 3) * 129 + e] = ((u64)mono_key(v.w) << 7) | (unsigned)e;
    }
    // ---- Phase 0b: load C0 table via float4
    {
        const float4* c4 = (const float4*)g_C0;
        float4* s4 = (float4*)C0s;
        #pragma unroll
        for (int i = 0; i < 4; ++i) s4[t + 1024 * i] = c4[t + 1024 * i];
    }
    __syncthreads();

    // ---- Phase 1: ranks. warp w -> freq w; lane handles e = l, +32, +64, +96
    {
        const u64* krow = ks + w * 129;
        u64 ke0 = krow[l];
        u64 ke1 = krow[l + 32];
        u64 ke2 = krow[l + 64];
        u64 ke3 = krow[l + 96];
        int c0 = 0, c1 = 0, c2 = 0, c3 = 0;
        #pragma unroll 16
        for (int m = 0; m < E; ++m) {
            u64 km = krow[m];               // warp-uniform broadcast
            c0 += (km < ke0);
            c1 += (km < ke1);
            c2 += (km < ke2);
            c3 += (km < ke3);
        }
        int* rrow = ranks + w * E;
        rrow[l]      = c0;
        rrow[l + 32] = c1;
        rrow[l + 64] = c2;
        rrow[l + 96] = c3;
    }
    __syncthreads();

    // ---- Phase 2: upper-triangle gather-accumulate
    const int j0 = 2 * w, j1 = 2 * w + 1, j2 = 126 - 2 * w, j3 = 127 - 2 * w;
    const char* C0b = (const char*)C0s;

    if (w < 16) {
        // rows j0,j1: groups 0..3 ; rows j2,j3: group 3 only   (10 groups)
        float a0[4] = {0,0,0,0}, a1[4] = {0,0,0,0};
        float a2 = 0.0f, a3 = 0.0f;
        for (int f = 0; f < F; ++f) {
            const int* rrow = ranks + f * E;
            int ckb0 = rrow[l]      << 2;
            int ckb1 = rrow[l + 32] << 2;
            int ckb2 = rrow[l + 64] << 2;
            int ckb3 = rrow[l + 96] << 2;
            const char* R0 = C0b + (rrow[j0] << 9);
            const char* R1 = C0b + (rrow[j1] << 9);
            const char* R2 = C0b + (rrow[j2] << 9);
            const char* R3 = C0b + (rrow[j3] << 9);
            a0[0] += *(const float*)(R0 + ckb0);
            a0[1] += *(const float*)(R0 + ckb1);
            a0[2] += *(const float*)(R0 + ckb2);
            a0[3] += *(const float*)(R0 + ckb3);
            a1[0] += *(const float*)(R1 + ckb0);
            a1[1] += *(const float*)(R1 + ckb1);
            a1[2] += *(const float*)(R1 + ckb2);
            a1[3] += *(const float*)(R1 + ckb3);
            a2    += *(const float*)(R2 + ckb3);
            a3    += *(const float*)(R3 + ckb3);
        }
        __syncthreads();   // everyone done reading C0s/ranks
        // stage upper triangle (k >= j only), scaled by 1/F
        const float s = 1.0f / (float)F;
        #pragma unroll
        for (int m = 0; m < 4; ++m) {
            int k = (m << 5) + l;
            if (k >= j0) T[j0 * 129 + k] = a0[m] * s;
            if (k >= j1) T[j1 * 129 + k] = a1[m] * s;
        }
        { int k = 96 + l; if (k >= j2) T[j2 * 129 + k] = a2 * s;
                          if (k >= j3) T[j3 * 129 + k] = a3 * s; }
    } else {
        // rows j0,j1: groups 1..3 ; rows j2,j3: groups 2..3   (10 groups)
        float a0[3] = {0,0,0}, a1[3] = {0,0,0};
        float a2[2] = {0,0},   a3[2] = {0,0};
        for (int f = 0; f < F; ++f) {
            const int* rrow = ranks + f * E;
            int ckb1 = rrow[l + 32] << 2;
            int ckb2 = rrow[l + 64] << 2;
            int ckb3 = rrow[l + 96] << 2;
            const char* R0 = C0b + (rrow[j0] << 9);
            const char* R1 = C0b + (rrow[j1] << 9);
            const char* R2 = C0b + (rrow[j2] << 9);
            const char* R3 = C0b + (rrow[j3] << 9);
            a0[0] += *(const float*)(R0 + ckb1);
            a0[1] += *(const float*)(R0 + ckb2);
            a0[2] += *(const float*)(R0 + ckb3);
            a1[0] += *(const float*)(R1 + ckb1);
            a1[1] += *(const float*)(R1 + ckb2);
            a1[2] += *(const float*)(R1 + ckb3);
            a2[0] += *(const float*)(R2 + ckb2);
            a2[1] += *(const float*)(R2 + ckb3);
            a3[0] += *(const float*)(R3 + ckb2);
            a3[1] += *(const float*)(R3 + ckb3);
        }
        __syncthreads();
        const float s = 1.0f / (float)F;
        #pragma unroll
        for (int m = 1; m < 4; ++m) {
            int k = (m << 5) + l;
            if (k >= j0) T[j0 * 129 + k] = a0[m - 1] * s;
            if (k >= j1) T[j1 * 129 + k] = a1[m - 1] * s;
        }
        #pragma unroll
        for (int m = 2; m < 4; ++m) {
            int k = (m << 5) + l;
            if (k >= j2) T[j2 * 129 + k] = a2[m - 2] * s;
            if (k >= j3) T[j3 * 129 + k] = a3[m - 2] * s;
        }
    }
    __syncthreads();

    // ---- Phase 3: mirrored writeout. Warp w -> rows 4w..4w+3, coalesced.
    float* o = out + (size_t)b * (E * E);
    #pragma unroll
    for (int jr = 0; jr < 4; ++jr) {
        int j = (w << 2) + jr;
        float* orow = o + j * E;
        #pragma unroll
        for (int m = 0; m < 4; ++m) {
            int k = (m << 5) + l;
            // both address forms hit bank (j+k)%32 -> conflict-free mix
            float v = (k >= j) ? T[j * 129 + k] : T[k * 129 + j];
            orow[k] = v;
        }
    }
}

extern "C" void kernel_launch(void* const* d_in, const int* in_sizes, int n_in,
                              void* d_out, int out_size) {
    const float* de = (const float*)d_in[0];
    float* out = (float*)d_out;
    int B = in_sizes[0] / (E * F);

    cudaFuncSetAttribute(spearman_main_kernel,
                         cudaFuncAttributeMaxDynamicSharedMemorySize, SMEM_TOTAL);

    build_c0_kernel<<<E, E>>>();
    spearman_main_kernel<<<B, 1024, SMEM_TOTAL>>>(de, out);
}

// round 4
// speedup vs baseline: 1.4026x; 1.0414x over previous
#include <cuda_runtime.h>
#include <cstdint>

#define E 128
#define F 32
typedef unsigned long long u64;

// smem layout (dynamic, bytes):
//   C0s     : 16384 floats        [0, 65536)
//   ks64    : 32*129 u64 keys     [65536, 98560)   (transposed, stride 129)
//   colpack : 32*32 uint2         [98560, 106752)  (pre-scaled col byte offsets)
//   rp      : 32*64 u32           [106752, 114944) (pre-scaled row byte offsets, paired)
//   ranks   : 32*128 int          [114944, 131328) (raw ranks, for repack)
// After phase 2 the front region is reused as the staging tile
//   T       : 128*129 floats      [0, 66048)
#define SMEM_C0     0
#define SMEM_KS     65536
#define SMEM_CP     98560
#define SMEM_RP     106752
#define SMEM_RANK   114944
#define SMEM_TOTAL  131328

__device__ float g_C0[E * E];

// Monotone map float -> uint preserving < order (no NaNs in input)
__device__ __forceinline__ unsigned mono_key(float x) {
    unsigned u = __float_as_uint(x);
    return u ^ ((unsigned)((int)u >> 31) | 0x80000000u);
}

// ---------------------------------------------------------------------------
// Fixed table C0[a,b] = (W0^2)[a,b] - s0[a]*s0[b]/(E-1),
// W0[a,b] = 1/(|a-b|+1), s0[a] = sum_b W0[b,a].
// ---------------------------------------------------------------------------
__global__ void build_c0_kernel() {
    __shared__ float inv[E];
    __shared__ float s0[E];
    int a = blockIdx.x;
    int b = threadIdx.x;
    inv[b] = 1.0f / (float)(b + 1);
    __syncthreads();
    float s = 0.0f;
    #pragma unroll 8
    for (int m = 0; m < E; ++m) s += inv[abs(m - b)];
    s0[b] = s;
    __syncthreads();
    float g = 0.0f;
    #pragma unroll 8
    for (int m = 0; m < E; ++m) g += inv[abs(m - a)] * inv[abs(m - b)];
    g_C0[a * E + b] = g - s0[a] * s0[b] * (1.0f / (float)(E - 1));
}

// ---------------------------------------------------------------------------
// Main kernel: one CTA per batch. 1024 threads = 32 warps.
// Phase 1: ranks via 64-bit keys (mono<<7 | e); write packed pre-scaled
//          offset arrays (col: <<2 byte offsets, row: <<9 byte offsets).
// Phase 2: upper triangle only. Warp w owns rows {2w,2w+1,126-2w,127-2w};
//          per f: 1 LDS.64 (cols) + 2 uniform LDS (rows) + 10 gathers.
// Phase 3: stage to smem tile (stride 129), mirror-read conflict-free,
//          coalesced writeout.
// ---------------------------------------------------------------------------
__global__ __launch_bounds__(1024, 1)
void spearman_main_kernel(const float* __restrict__ de, float* __restrict__ out) {
    extern __shared__ char smem[];
    float*    C0s   = (float*)   (smem + SMEM_C0);
    u64*      ks    = (u64*)     (smem + SMEM_KS);
    uint2*    cp    = (uint2*)   (smem + SMEM_CP);
    unsigned* rp    = (unsigned*)(smem + SMEM_RP);
    int*      ranks = (int*)     (smem + SMEM_RANK);
    float*    T     = (float*)   (smem + SMEM_C0);   // reuse after phase 2

    const int t = threadIdx.x;
    const int b = blockIdx.x;
    const int w = t >> 5;       // warp id == frequency band (phase 1)
    const int l = t & 31;       // lane

    // ---- Phase 0a: load de[b] as float4, store transposed 64-bit keys
    {
        const float4* din4 = (const float4*)(de + (size_t)b * (E * F));
        float4 v = din4[t];                 // e = t/8, f = (t%8)*4 .. +3
        int e  = t >> 3;
        int f0 = (t & 7) << 2;
        ks[(f0 + 0) * 129 + e] = ((u64)mono_key(v.x) << 7) | (unsigned)e;
        ks[(f0 + 1) * 129 + e] = ((u64)mono_key(v.y) << 7) | (unsigned)e;
        ks[(f0 + 2) * 129 + e] = ((u64)mono_key(v.z) << 7) | (unsigned)e;
        ks[(f0 + 3) * 129 + e] = ((u64)mono_key(v.w) << 7) | (unsigned)e;
    }
    // ---- Phase 0b: load C0 table via float4
    {
        const float4* c4 = (const float4*)g_C0;
        float4* s4 = (float4*)C0s;
        #pragma unroll
        for (int i = 0; i < 4; ++i) s4[t + 1024 * i] = c4[t + 1024 * i];
    }
    __syncthreads();

    // ---- Phase 1: ranks. warp w -> freq w; lane handles e = l, +32, +64, +96
    {
        const u64* krow = ks + w * 129;
        u64 ke0 = krow[l];
        u64 ke1 = krow[l + 32];
        u64 ke2 = krow[l + 64];
        u64 ke3 = krow[l + 96];
        int c0 = 0, c1 = 0, c2 = 0, c3 = 0;
        #pragma unroll 16
        for (int m = 0; m < E; ++m) {
            u64 km = krow[m];               // warp-uniform broadcast
            c0 += (km < ke0);
            c1 += (km < ke1);
            c2 += (km < ke2);
            c3 += (km < ke3);
        }
        // packed pre-scaled column byte offsets (rank*4)
        cp[w * 32 + l] = make_uint2(((unsigned)c0 << 2) | ((unsigned)c1 << 18),
                                    ((unsigned)c2 << 2) | ((unsigned)c3 << 18));
        int* rrow = ranks + w * E;
        rrow[l]      = c0;
        rrow[l + 32] = c1;
        rrow[l + 64] = c2;
        rrow[l + 96] = c3;
    }
    __syncthreads();

    // ---- Phase 1b: repack row offsets (rank*512), two rows per word.
    // rp[f*64 + p] = (rank[2p]<<9) | (rank[2p+1]<<25)
    {
        const int f = w;
        const int* rrow = ranks + f * E;
        #pragma unroll
        for (int pi = 0; pi < 2; ++pi) {
            int p = l + 32 * pi;
            unsigned rlo = (unsigned)rrow[2 * p]     << 9;
            unsigned rhi = (unsigned)rrow[2 * p + 1] << 25;
            rp[f * 64 + p] = rlo | rhi;
        }
    }
    __syncthreads();

    // ---- Phase 2: upper-triangle gather-accumulate
    const int j0 = 2 * w, j1 = 2 * w + 1, j2 = 126 - 2 * w, j3 = 127 - 2 * w;
    const char* C0b = (const char*)C0s;

    if (w < 16) {
        // rows j0,j1: groups 0..3 ; rows j2,j3: group 3 only   (10 gathers)
        float a0[4] = {0,0,0,0}, a1[4] = {0,0,0,0};
        float a2 = 0.0f, a3 = 0.0f;
        for (int f = 0; f < F; ++f) {
            uint2 c = cp[f * 32 + l];                  // LDS.64, conflict-free
            unsigned rlohi = rp[f * 64 + w];           // rows j0,j1 (uniform)
            unsigned rhilo = rp[f * 64 + (63 - w)];    // rows j2,j3 (uniform)
            int ckb0 = c.x & 0xFFFF, ckb1 = c.x >> 16;
            int ckb2 = c.y & 0xFFFF, ckb3 = c.y >> 16;
            const char* R0 = C0b + (rlohi & 0xFFFF);
            const char* R1 = C0b + (rlohi >> 16);
            const char* R2 = C0b + (rhilo & 0xFFFF);
            const char* R3 = C0b + (rhilo >> 16);
            a0[0] += *(const float*)(R0 + ckb0);
            a0[1] += *(const float*)(R0 + ckb1);
            a0[2] += *(const float*)(R0 + ckb2);
            a0[3] += *(const float*)(R0 + ckb3);
            a1[0] += *(const float*)(R1 + ckb0);
            a1[1] += *(const float*)(R1 + ckb1);
            a1[2] += *(const float*)(R1 + ckb2);
            a1[3] += *(const float*)(R1 + ckb3);
            a2    += *(const float*)(R2 + ckb3);
            a3    += *(const float*)(R3 + ckb3);
        }
        __syncthreads();   // everyone done reading C0s/cp/rp
        const float s = 1.0f / (float)F;
        #pragma unroll
        for (int m = 0; m < 4; ++m) {
            int k = (m << 5) + l;
            if (k >= j0) T[j0 * 129 + k] = a0[m] * s;
            if (k >= j1) T[j1 * 129 + k] = a1[m] * s;
        }
        { int k = 96 + l; if (k >= j2) T[j2 * 129 + k] = a2 * s;
                          if (k >= j3) T[j3 * 129 + k] = a3 * s; }
    } else {
        // rows j0,j1: groups 1..3 ; rows j2,j3: groups 2..3   (10 gathers)
        float a0[3] = {0,0,0}, a1[3] = {0,0,0};
        float a2[2] = {0,0},   a3[2] = {0,0};
        for (int f = 0; f < F; ++f) {
            uint2 c = cp[f * 32 + l];
            unsigned rlohi = rp[f * 64 + w];
            unsigned rhilo = rp[f * 64 + (63 - w)];
            int ckb1 = c.x >> 16;
            int ckb2 = c.y & 0xFFFF, ckb3 = c.y >> 16;
            const char* R0 = C0b + (rlohi & 0xFFFF);
            const char* R1 = C0b + (rlohi >> 16);
            const char* R2 = C0b + (rhilo & 0xFFFF);
            const char* R3 = C0b + (rhilo >> 16);
            a0[0] += *(const float*)(R0 + ckb1);
            a0[1] += *(const float*)(R0 + ckb2);
            a0[2] += *(const float*)(R0 + ckb3);
            a1[0] += *(const float*)(R1 + ckb1);
            a1[1] += *(const float*)(R1 + ckb2);
            a1[2] += *(const float*)(R1 + ckb3);
            a2[0] += *(const float*)(R2 + ckb2);
            a2[1] += *(const float*)(R2 + ckb3);
            a3[0] += *(const float*)(R3 + ckb2);
            a3[1] += *(const float*)(R3 + ckb3);
        }
        __syncthreads();
        const float s = 1.0f / (float)F;
        #pragma unroll
        for (int m = 1; m < 4; ++m) {
            int k = (m << 5) + l;
            if (k >= j0) T[j0 * 129 + k] = a0[m - 1] * s;
            if (k >= j1) T[j1 * 129 + k] = a1[m - 1] * s;
        }
        #pragma unroll
        for (int m = 2; m < 4; ++m) {
            int k = (m << 5) + l;
            if (k >= j2) T[j2 * 129 + k] = a2[m - 2] * s;
            if (k >= j3) T[j3 * 129 + k] = a3[m - 2] * s;
        }
    }
    __syncthreads();

    // ---- Phase 3: mirrored writeout. Warp w -> rows 4w..4w+3, coalesced.
    float* o = out + (size_t)b * (E * E);
    #pragma unroll
    for (int jr = 0; jr < 4; ++jr) {
        int j = (w << 2) + jr;
        float* orow = o + j * E;
        #pragma unroll
        for (int m = 0; m < 4; ++m) {
            int k = (m << 5) + l;
            // both address forms hit bank (j+k)%32 -> conflict-free mix
            float v = (k >= j) ? T[j * 129 + k] : T[k * 129 + j];
            orow[k] = v;
        }
    }
}

extern "C" void kernel_launch(void* const* d_in, const int* in_sizes, int n_in,
                              void* d_out, int out_size) {
    const float* de = (const float*)d_in[0];
    float* out = (float*)d_out;
    int B = in_sizes[0] / (E * F);

    cudaFuncSetAttribute(spearman_main_kernel,
                         cudaFuncAttributeMaxDynamicSharedMemorySize, SMEM_TOTAL);

    build_c0_kernel<<<E, E>>>();
    spearman_main_kernel<<<B, 1024, SMEM_TOTAL>>>(de, out);
}

// round 5
// speedup vs baseline: 1.4211x; 1.0132x over previous
#include <cuda_runtime.h>
#include <cstdint>

#define E 128
#define F 32
typedef unsigned long long u64;

// smem layout (dynamic, bytes):
//   C0s : 16384 floats        [0, 65536)
//   ks  : 32*130 u64 keys     [65536, 98816)   (transposed, stride 130 -> 16B aligned rows)
//   cp  : 32*32 uint2         [98816, 107008)  (pre-scaled col byte offsets, packed 16b)
//   rp  : 32*64 u32           [107008, 115200) (pre-scaled row byte offsets, paired 16b)
// After phase 2 the front region is reused as the staging tile
//   T   : 128*129 floats      [0, 66048)
#define SMEM_C0     0
#define SMEM_KS     65536
#define SMEM_CP     98816
#define SMEM_RP     107008
#define SMEM_TOTAL  115200

__device__ float g_C0[E * E];

// Monotone map float -> uint preserving < order (no NaNs in input)
__device__ __forceinline__ unsigned mono_key(float x) {
    unsigned u = __float_as_uint(x);
    return u ^ ((unsigned)((int)u >> 31) | 0x80000000u);
}

// ---------------------------------------------------------------------------
// Fixed table C0[a,b] = (W0^2)[a,b] - s0[a]*s0[b]/(E-1),
// W0[a,b] = 1/(|a-b|+1), s0[a] = sum_b W0[b,a].
// ---------------------------------------------------------------------------
__global__ void build_c0_kernel() {
    __shared__ float inv[E];
    __shared__ float s0[E];
    int a = blockIdx.x;
    int b = threadIdx.x;
    inv[b] = 1.0f / (float)(b + 1);
    __syncthreads();
    float s = 0.0f;
    #pragma unroll 8
    for (int m = 0; m < E; ++m) s += inv[abs(m - b)];
    s0[b] = s;
    __syncthreads();
    float g = 0.0f;
    #pragma unroll 8
    for (int m = 0; m < E; ++m) g += inv[abs(m - a)] * inv[abs(m - b)];
    g_C0[a * E + b] = g - s0[a] * s0[b] * (1.0f / (float)(E - 1));
}

// ---------------------------------------------------------------------------
// Main kernel: one CTA per batch. 1024 threads = 32 warps.
// Phase 1: ranks via 64-bit keys (mono<<7 | e), LDS.128 paired key loads;
//          cp (col offsets <<2, 16b-packed) written directly; rp (row offsets
//          <<9, paired) built in-warp via shuffles -- no ranks array.
// Phase 2: upper triangle only, f-loop unrolled x2 for LDS-level parallelism.
//          Warp w owns rows {2w,2w+1,126-2w,127-2w}; 10 gathers per f.
// Phase 3: stage to smem tile (stride 129), mirror-read conflict-free,
//          coalesced writeout.
// ---------------------------------------------------------------------------
__global__ __launch_bounds__(1024, 1)
void spearman_main_kernel(const float* __restrict__ de, float* __restrict__ out) {
    extern __shared__ char smem[];
    float*    C0s = (float*)   (smem + SMEM_C0);
    u64*      ks  = (u64*)     (smem + SMEM_KS);
    uint2*    cp  = (uint2*)   (smem + SMEM_CP);
    unsigned* rp  = (unsigned*)(smem + SMEM_RP);
    float*    T   = (float*)   (smem + SMEM_C0);   // reuse after phase 2

    const int t = threadIdx.x;
    const int b = blockIdx.x;
    const int w = t >> 5;       // warp id == frequency band (phase 1)
    const int l = t & 31;       // lane

    // ---- Phase 0a: load de[b] as float4, store transposed 64-bit keys
    {
        const float4* din4 = (const float4*)(de + (size_t)b * (E * F));
        float4 v = din4[t];                 // e = t/8, f = (t%8)*4 .. +3
        int e  = t >> 3;
        int f0 = (t & 7) << 2;
        ks[(f0 + 0) * 130 + e] = ((u64)mono_key(v.x) << 7) | (unsigned)e;
        ks[(f0 + 1) * 130 + e] = ((u64)mono_key(v.y) << 7) | (unsigned)e;
        ks[(f0 + 2) * 130 + e] = ((u64)mono_key(v.z) << 7) | (unsigned)e;
        ks[(f0 + 3) * 130 + e] = ((u64)mono_key(v.w) << 7) | (unsigned)e;
    }
    // ---- Phase 0b: load C0 table via float4
    {
        const float4* c4 = (const float4*)g_C0;
        float4* s4 = (float4*)C0s;
        #pragma unroll
        for (int i = 0; i < 4; ++i) s4[t + 1024 * i] = c4[t + 1024 * i];
    }
    __syncthreads();

    // ---- Phase 1: ranks. warp w -> freq w; lane handles e = l, +32, +64, +96
    {
        const u64* krow = ks + w * 130;
        u64 ke0 = krow[l];
        u64 ke1 = krow[l + 32];
        u64 ke2 = krow[l + 64];
        u64 ke3 = krow[l + 96];
        const uint4* krow4 = (const uint4*)krow;   // 130*8 = 1040 B rows, 16B aligned
        int c0 = 0, c1 = 0, c2 = 0, c3 = 0;
        #pragma unroll 8
        for (int m2 = 0; m2 < 64; ++m2) {
            uint4 q = krow4[m2];                   // LDS.128 broadcast: 2 keys
            u64 ka = (u64)q.x | ((u64)q.y << 32);
            u64 kb = (u64)q.z | ((u64)q.w << 32);
            c0 += (ka < ke0) + (kb < ke0);
            c1 += (ka < ke1) + (kb < ke1);
            c2 += (ka < ke2) + (kb < ke2);
            c3 += (ka < ke3) + (kb < ke3);
        }
        // packed pre-scaled column byte offsets (rank*4)
        cp[w * 32 + l] = make_uint2(((unsigned)c0 << 2) | ((unsigned)c1 << 18),
                                    ((unsigned)c2 << 2) | ((unsigned)c3 << 18));
        // row byte offsets (rank*512), two rows per word, built via shuffles.
        // rank of electrode e lives in lane e&31, slot e>>5.
        const unsigned full = 0xFFFFFFFFu;
        int e0s = (2 * l) & 31;
        int e1s = (2 * l + 1) & 31;
        bool hi = (l >= 16);
        int rA0 = __shfl_sync(full, c0, e0s);
        int rB0 = __shfl_sync(full, c1, e0s);
        int rA1 = __shfl_sync(full, c0, e1s);
        int rB1 = __shfl_sync(full, c1, e1s);
        rp[w * 64 + l] = ((unsigned)(hi ? rB0 : rA0) << 9)
                       | ((unsigned)(hi ? rB1 : rA1) << 25);
        int rC0 = __shfl_sync(full, c2, e0s);
        int rD0 = __shfl_sync(full, c3, e0s);
        int rC1 = __shfl_sync(full, c2, e1s);
        int rD1 = __shfl_sync(full, c3, e1s);
        rp[w * 64 + 32 + l] = ((unsigned)(hi ? rD0 : rC0) << 9)
                            | ((unsigned)(hi ? rD1 : rC1) << 25);
    }
    __syncthreads();

    // ---- Phase 2: upper-triangle gather-accumulate, f unrolled x2
    const int j0 = 2 * w, j1 = 2 * w + 1, j2 = 126 - 2 * w, j3 = 127 - 2 * w;
    const char* C0b = (const char*)C0s;

    if (w < 16) {
        // rows j0,j1: groups 0..3 ; rows j2,j3: group 3 only   (10 gathers/f)
        float a0[4] = {0,0,0,0}, a1[4] = {0,0,0,0};
        float a2 = 0.0f, a3 = 0.0f;
        for (int f = 0; f < F; f += 2) {
            uint2 cA = cp[f * 32 + l];
            uint2 cB = cp[(f + 1) * 32 + l];
            unsigned rAlo = rp[f * 64 + w];
            unsigned rAhi = rp[f * 64 + (63 - w)];
            unsigned rBlo = rp[(f + 1) * 64 + w];
            unsigned rBhi = rp[(f + 1) * 64 + (63 - w)];
            #pragma unroll
            for (int u = 0; u < 2; ++u) {
                uint2 c = u ? cB : cA;
                unsigned rlo = u ? rBlo : rAlo;
                unsigned rhi = u ? rBhi : rAhi;
                int ckb0 = c.x & 0xFFFF, ckb1 = c.x >> 16;
                int ckb2 = c.y & 0xFFFF, ckb3 = c.y >> 16;
                const char* R0 = C0b + (rlo & 0xFFFF);
                const char* R1 = C0b + (rlo >> 16);
                const char* R2 = C0b + (rhi & 0xFFFF);
                const char* R3 = C0b + (rhi >> 16);
                a0[0] += *(const float*)(R0 + ckb0);
                a0[1] += *(const float*)(R0 + ckb1);
                a0[2] += *(const float*)(R0 + ckb2);
                a0[3] += *(const float*)(R0 + ckb3);
                a1[0] += *(const float*)(R1 + ckb0);
                a1[1] += *(const float*)(R1 + ckb1);
                a1[2] += *(const float*)(R1 + ckb2);
                a1[3] += *(const float*)(R1 + ckb3);
                a2    += *(const float*)(R2 + ckb3);
                a3    += *(const float*)(R3 + ckb3);
            }
        }
        __syncthreads();   // everyone done reading C0s/cp/rp
        const float s = 1.0f / (float)F;
        #pragma unroll
        for (int m = 0; m < 4; ++m) {
            int k = (m << 5) + l;
            if (k >= j0) T[j0 * 129 + k] = a0[m] * s;
            if (k >= j1) T[j1 * 129 + k] = a1[m] * s;
        }
        { int k = 96 + l; if (k >= j2) T[j2 * 129 + k] = a2 * s;
                          if (k >= j3) T[j3 * 129 + k] = a3 * s; }
    } else {
        // rows j0,j1: groups 1..3 ; rows j2,j3: groups 2..3   (10 gathers/f)
        float a0[3] = {0,0,0}, a1[3] = {0,0,0};
        float a2[2] = {0,0},   a3[2] = {0,0};
        for (int f = 0; f < F; f += 2) {
            uint2 cA = cp[f * 32 + l];
            uint2 cB = cp[(f + 1) * 32 + l];
            unsigned rAlo = rp[f * 64 + w];
            unsigned rAhi = rp[f * 64 + (63 - w)];
            unsigned rBlo = rp[(f + 1) * 64 + w];
            unsigned rBhi = rp[(f + 1) * 64 + (63 - w)];
            #pragma unroll
            for (int u = 0; u < 2; ++u) {
                uint2 c = u ? cB : cA;
                unsigned rlo = u ? rBlo : rAlo;
                unsigned rhi = u ? rBhi : rAhi;
                int ckb1 = c.x >> 16;
                int ckb2 = c.y & 0xFFFF, ckb3 = c.y >> 16;
                const char* R0 = C0b + (rlo & 0xFFFF);
                const char* R1 = C0b + (rlo >> 16);
                const char* R2 = C0b + (rhi & 0xFFFF);
                const char* R3 = C0b + (rhi >> 16);
                a0[0] += *(const float*)(R0 + ckb1);
                a0[1] += *(const float*)(R0 + ckb2);
                a0[2] += *(const float*)(R0 + ckb3);
                a1[0] += *(const float*)(R1 + ckb1);
                a1[1] += *(const float*)(R1 + ckb2);
                a1[2] += *(const float*)(R1 + ckb3);
                a2[0] += *(const float*)(R2 + ckb2);
                a2[1] += *(const float*)(R2 + ckb3);
                a3[0] += *(const float*)(R3 + ckb2);
                a3[1] += *(const float*)(R3 + ckb3);
            }
        }
        __syncthreads();
        const float s = 1.0f / (float)F;
        #pragma unroll
        for (int m = 1; m < 4; ++m) {
            int k = (m << 5) + l;
            if (k >= j0) T[j0 * 129 + k] = a0[m - 1] * s;
            if (k >= j1) T[j1 * 129 + k] = a1[m - 1] * s;
        }
        #pragma unroll
        for (int m = 2; m < 4; ++m) {
            int k = (m << 5) + l;
            if (k >= j2) T[j2 * 129 + k] = a2[m - 2] * s;
            if (k >= j3) T[j3 * 129 + k] = a3[m - 2] * s;
        }
    }
    __syncthreads();

    // ---- Phase 3: mirrored writeout. Warp w -> rows 4w..4w+3, coalesced.
    float* o = out + (size_t)b * (E * E);
    #pragma unroll
    for (int jr = 0; jr < 4; ++jr) {
        int j = (w << 2) + jr;
        float* orow = o + j * E;
        #pragma unroll
        for (int m = 0; m < 4; ++m) {
            int k = (m << 5) + l;
            // both address forms hit bank (j+k)%32 -> conflict-free mix
            float v = (k >= j) ? T[j * 129 + k] : T[k * 129 + j];
            orow[k] = v;
        }
    }
}

extern "C" void kernel_launch(void* const* d_in, const int* in_sizes, int n_in,
                              void* d_out, int out_size) {
    const float* de = (const float*)d_in[0];
    float* out = (float*)d_out;
    int B = in_sizes[0] / (E * F);

    cudaFuncSetAttribute(spearman_main_kernel,
                         cudaFuncAttributeMaxDynamicSharedMemorySize, SMEM_TOTAL);

    build_c0_kernel<<<E, E>>>();
    spearman_main_kernel<<<B, 1024, SMEM_TOTAL>>>(de, out);
}